// round 13
// baseline (speedup 1.0000x reference)
#include <cuda_runtime.h>
#include <cuda_fp16.h>
#include <cstdint>
#include <cstddef>

#define T_STEPS 2048
#define N_ENV   256
#define HID     128
#define G3      384
#define IDIM    128
#define M_TOTAL (T_STEPS*N_ENV)
#define LDA     132
#define EPC     8            // envs per CTA (k2)
#define NCTA2   (N_ENV/EPC)  // 32 CTAs
#define GISTR   388          // gi/ghp row stride (floats): %32==4 -> bank-spread
#define GISLOT  (EPC*GISTR)

// Scratch for gi = x @ w_ih^T + b_ih : [M_TOTAL, G3] fp32 (805 MB)
__device__ float g_gi[(size_t)M_TOTAL * G3];

// ---------------------------------------------------------------------------
// helpers (sm_103 base target — NO tcgen05)
// ---------------------------------------------------------------------------
__device__ __forceinline__ unsigned f2tf(float f){
  unsigned u; asm("cvt.rna.tf32.f32 %0, %1;" : "=r"(u) : "f"(f)); return u;
}
__device__ __forceinline__ void mma8(float* c, const unsigned* a, const unsigned* b){
  asm volatile("mma.sync.aligned.m16n8k8.row.col.f32.tf32.tf32.f32 "
      "{%0,%1,%2,%3}, {%4,%5,%6,%7}, {%8,%9}, {%0,%1,%2,%3};"
      : "+f"(c[0]), "+f"(c[1]), "+f"(c[2]), "+f"(c[3])
      : "r"(a[0]), "r"(a[1]), "r"(a[2]), "r"(a[3]), "r"(b[0]), "r"(b[1]));
}
__device__ __forceinline__ void hmma16(float* c, const unsigned* a, unsigned b0, unsigned b1){
  asm volatile("mma.sync.aligned.m16n8k16.row.col.f32.f16.f16.f32 "
      "{%0,%1,%2,%3}, {%4,%5,%6,%7}, {%8,%9}, {%0,%1,%2,%3};"
      : "+f"(c[0]), "+f"(c[1]), "+f"(c[2]), "+f"(c[3])
      : "r"(a[0]), "r"(a[1]), "r"(a[2]), "r"(a[3]), "r"(b0), "r"(b1));
}
__device__ __forceinline__ void ldsm4(unsigned* r, unsigned addr){
  asm volatile("ldmatrix.sync.aligned.m8n8.x4.shared.b16 {%0,%1,%2,%3}, [%4];"
      : "=r"(r[0]), "=r"(r[1]), "=r"(r[2]), "=r"(r[3]) : "r"(addr));
}
__device__ __forceinline__ unsigned lds32(unsigned a){
  unsigned v; asm volatile("ld.shared.b32 %0, [%1];" : "=r"(v) : "r"(a)); return v;
}
__device__ __forceinline__ void cp16(void* dst, const void* src){
  unsigned s = (unsigned)__cvta_generic_to_shared(dst);
  asm volatile("cp.async.cg.shared.global [%0], [%1], 16;" :: "r"(s), "l"(src));
}
__device__ __forceinline__ unsigned smem_u32(const void* p){
  return (unsigned)__cvta_generic_to_shared(p);
}
__device__ __forceinline__ unsigned pkh2(float a, float b){
  __half2 h = __floats2half2_rn(a, b);
  unsigned u; memcpy(&u, &h, 4); return u;
}
__device__ __forceinline__ float tanha(float x){
  float y; asm("tanh.approx.f32 %0, %1;" : "=f"(y) : "f"(x)); return y;
}
__device__ __forceinline__ float siga(float x){
  return fmaf(0.5f, tanha(0.5f*x), 0.5f);
}

// ---------------------------------------------------------------------------
// K1: gi = x @ w_ih^T + b_ih   (tf32 mma.sync) — exact R5 version (passing)
// ---------------------------------------------------------------------------
__global__ void __launch_bounds__(256) k1_gi(const float* __restrict__ x,
                                             const float* __restrict__ w_ih,
                                             const float* __restrict__ b_ih){
  extern __shared__ float sm[];
  float* Bs   = sm;
  float* As   = sm + 128*LDA;
  float* bias = sm + 3*128*LDA;

  const int tid  = threadIdx.x;
  const int nb   = blockIdx.x;
  const int slab = blockIdx.y;
  const int gbase = nb * 128;

  for (int idx = tid; idx < 128*32; idx += 256){
    int r = idx >> 5, c4 = idx & 31;
    float4 v = reinterpret_cast<const float4*>(w_ih + (size_t)(gbase + r)*IDIM)[c4];
    float* d = Bs + r*LDA + c4*4;
    d[0] = __uint_as_float(f2tf(v.x));
    d[1] = __uint_as_float(f2tf(v.y));
    d[2] = __uint_as_float(f2tf(v.z));
    d[3] = __uint_as_float(f2tf(v.w));
  }
  if (tid < 128) bias[tid] = b_ih[gbase + tid];

  const int lane = tid & 31, wid = tid >> 5;
  const int wm = wid >> 1, wn = wid & 1;
  const int grp = lane >> 2, qid = lane & 3;

  {
    const float* srcb = x + (size_t)slab * 128 * IDIM;
    #pragma unroll
    for (int i = 0; i < 16; i++){
      int c = tid + 256*i;
      int r = c >> 5, c16 = c & 31;
      cp16(As + r*LDA + c16*4, srcb + (size_t)r*IDIM + c16*4);
    }
    asm volatile("cp.async.commit_group;");
  }

  for (int it = 0; it < 32; it++){
    const int buf = it & 1;
    if (it + 1 < 32){
      int mt = slab + (it+1)*128;
      const float* srcb = x + (size_t)mt * 128 * IDIM;
      float* dstb = As + ((it+1)&1)*128*LDA;
      #pragma unroll
      for (int i = 0; i < 16; i++){
        int c = tid + 256*i;
        int r = c >> 5, c16 = c & 31;
        cp16(dstb + r*LDA + c16*4, srcb + (size_t)r*IDIM + c16*4);
      }
      asm volatile("cp.async.commit_group;");
      asm volatile("cp.async.wait_group 1;");
    } else {
      asm volatile("cp.async.wait_group 0;");
    }
    __syncthreads();

    float c[2][8][4];
    #pragma unroll
    for (int am=0;am<2;am++)
      #pragma unroll
      for(int an=0;an<8;an++)
        #pragma unroll
        for(int k=0;k<4;k++) c[am][an][k]=0.f;

    const float* A = As + buf*128*LDA;
    for (int k0 = 0; k0 < 128; k0 += 8){
      unsigned af[2][4];
      #pragma unroll
      for (int am=0; am<2; am++){
        int r0 = wm*32 + am*16 + grp;
        af[am][0] = f2tf(A[r0*LDA + k0 + qid]);
        af[am][1] = f2tf(A[(r0+8)*LDA + k0 + qid]);
        af[am][2] = f2tf(A[r0*LDA + k0 + qid + 4]);
        af[am][3] = f2tf(A[(r0+8)*LDA + k0 + qid + 4]);
      }
      unsigned bf[8][2];
      #pragma unroll
      for (int an=0; an<8; an++){
        int nr = wn*64 + an*8 + grp;
        bf[an][0] = __float_as_uint(Bs[nr*LDA + k0 + qid]);
        bf[an][1] = __float_as_uint(Bs[nr*LDA + k0 + qid + 4]);
      }
      #pragma unroll
      for (int am=0; am<2; am++)
        #pragma unroll
        for (int an=0; an<8; an++)
          mma8(c[am][an], af[am], bf[an]);
    }
    __syncthreads();

    const int mrow = (slab + it*128) * 128;
    #pragma unroll
    for (int am=0; am<2; am++){
      int r0 = mrow + wm*32 + am*16 + grp;
      #pragma unroll
      for (int an=0; an<8; an++){
        int colL = wn*64 + an*8 + 2*qid;
        float b0 = bias[colL], b1 = bias[colL+1];
        float2 v0 = make_float2(c[am][an][0]+b0, c[am][an][1]+b1);
        float2 v1 = make_float2(c[am][an][2]+b0, c[am][an][3]+b1);
        *reinterpret_cast<float2*>(&g_gi[(size_t)r0*G3 + gbase + colL]) = v0;
        *reinterpret_cast<float2*>(&g_gi[(size_t)(r0+8)*G3 + gbase + colL]) = v1;
      }
    }
  }
}

// ---------------------------------------------------------------------------
// K2: HMMA GRU scan, gate-triple co-located + K-SPLIT. 32 CTAs x 512 thr.
// Warps 0-7 (wk=0) accumulate k 0..63; warps 8-15 (wk=1) k 64..127 for the
// SAME (G, j, e) fragments. High half STS partials -> barrier -> low half
// combines + gates (tanh.approx: 3 MUFU/unit) -> h' regs + fp16 hhi/hlo STS.
// Split precision: acc += Whi*hhi + Whi*hlo + Wlo*hhi (exact-split W and h).
// ---------------------------------------------------------------------------
// smem layout (bytes)
#define WLO_OFF 0          // Wlo fp16 [384][136]   (104448)
#define HHI_OFF 104448     // hhi fp16 [8][136]     (2176)
#define HLO_OFF 106624     // hlo fp16 [8][136]     (2176)
#define GHP_OFF 108800     // gh partials fp32 [8][388] (12416)
#define GI_OFF  121216     // gi ring [4][8][388]   (49664)
#define MK_OFF  170880     // mask ring [4][8]      (128)
#define K2_SMEM 171008

__global__ void __launch_bounds__(512, 1) k2_scan(
    const float* __restrict__ h0,
    const float* __restrict__ masks,
    const float* __restrict__ w_hh,
    const float* __restrict__ b_hh,
    float* __restrict__ outs,
    float* __restrict__ h_final)
{
  extern __shared__ __align__(1024) char SM[];
  __half* wloS = (__half*)(SM + WLO_OFF);
  __half* hhiS = (__half*)(SM + HHI_OFF);
  __half* hloS = (__half*)(SM + HLO_OFF);
  float*  ghpS = (float*)(SM + GHP_OFF);
  float*  giS  = (float*)(SM + GI_OFF);
  float*  mS   = (float*)(SM + MK_OFF);

  const int g    = threadIdx.x;       // 0..511
  const int wid  = g >> 5;            // 0..15
  const int lane = g & 31;
  const int w8   = wid & 7;           // row-group warp id
  const int wk   = wid >> 3;          // k-half: 0 -> k 0..63, 1 -> k 64..127
  const int grp  = lane >> 2;
  const int qid  = lane & 3;
  const int e0   = blockIdx.x * EPC;
  const int J    = 16*w8 + grp;       // gate index base (0..127)
  const int E    = 2*qid;             // env base (0..7)
  const bool low = (wk == 0);
  const size_t OUT_STRIDE = (size_t)N_ENV*HID;

  // ---- Whi fragments in regs: [3 gates][4 local ksteps][4] = 48 regs ----
  unsigned whi[3][4][4];
  #pragma unroll
  for (int G = 0; G < 3; G++){
    #pragma unroll
    for (int kd = 0; kd < 4; kd++){
      int r0 = G*128 + J;
      int c0 = (wk*4 + kd)*16 + qid*2;
      const float* w0 = w_hh + (size_t)r0*HID + c0;
      const float* w1 = w_hh + (size_t)(r0+8)*HID + c0;
      whi[G][kd][0] = pkh2(w0[0], w0[1]);
      whi[G][kd][1] = pkh2(w1[0], w1[1]);
      whi[G][kd][2] = pkh2(w0[8], w0[9]);
      whi[G][kd][3] = pkh2(w1[8], w1[9]);
    }
  }
  // ---- Wlo = W - fp16(W) into smem (rows padded to 136 halves) ----
  for (int idx = g; idx < G3*HID; idx += 512){
    int r = idx >> 7, c = idx & 127;
    float wv = w_hh[idx];
    float hi = __half2float(__float2half_rn(wv));
    wloS[r*136 + c] = __float2half_rn(wv - hi);
  }
  // ---- biases in regs (gate threads = low half) ----
  const float bR0 = b_hh[J],     bR1 = b_hh[J+8];
  const float bZ0 = b_hh[128+J], bZ1 = b_hh[128+J+8];
  const float bN0 = b_hh[256+J], bN1 = b_hh[256+J+8];

  // ---- h master in regs on LOW warps (4 units) + hhi/hlo init ----
  float h00=0.f, h01=0.f, h10=0.f, h11=0.f;
  if (low){
    h00 = h0[(size_t)(e0+E  )*HID + J];
    h01 = h0[(size_t)(e0+E+1)*HID + J];
    h10 = h0[(size_t)(e0+E  )*HID + J+8];
    h11 = h0[(size_t)(e0+E+1)*HID + J+8];
    __half a;
    a = __float2half_rn(h00); hhiS[E*136+J]       = a; hloS[E*136+J]       = __float2half_rn(h00-__half2float(a));
    a = __float2half_rn(h01); hhiS[(E+1)*136+J]   = a; hloS[(E+1)*136+J]   = __float2half_rn(h01-__half2float(a));
    a = __float2half_rn(h10); hhiS[E*136+J+8]     = a; hloS[E*136+J+8]     = __float2half_rn(h10-__half2float(a));
    a = __float2half_rn(h11); hhiS[(E+1)*136+J+8] = a; hloS[(E+1)*136+J+8] = __float2half_rn(h11-__half2float(a));
  }

  // ---- gi/mask ring prologue: slots 0 and 1 ----
  #pragma unroll
  for (int pt = 0; pt < 2; pt++){
    const float* src = g_gi + ((size_t)pt*N_ENV + e0)*G3;
    #pragma unroll
    for (int i = 0; i < 2; i++){
      int ci = g + 512*i;               // 0..1023; need 0..767
      if (ci < 768){
        int e = ci / 96, c = ci % 96;
        cp16(giS + pt*GISLOT + e*GISTR + 4*c, src + (size_t)e*G3 + 4*c);
      }
    }
    if (g < 2) cp16(mS + pt*EPC + 4*g, masks + (size_t)pt*N_ENV + e0 + 4*g);
    asm volatile("cp.async.commit_group;");
  }
  asm volatile("cp.async.wait_group 1;");   // slot 0 ready
  __syncthreads();

  // ---- per-lane smem addresses (k offset = wk*64 halves = wk*128 bytes) ----
  const unsigned lmrow = (lane & 7) + ((lane >> 3) & 1) * 8;
  const unsigned lmcol = ((lane >> 4) & 1) * 8;
  unsigned lmb[3];
  #pragma unroll
  for (int G = 0; G < 3; G++)
    lmb[G] = smem_u32(wloS) + ((G*128 + 16*w8 + lmrow)*136 + lmcol)*2 + wk*128;
  const unsigned hhib = smem_u32(hhiS) + (grp*136 + qid*2)*2 + wk*128;
  const unsigned hlob = smem_u32(hloS) + (grp*136 + qid*2)*2 + wk*128;

  #pragma unroll 1
  for (int t = 0; t < T_STEPS; t++){
    // ---- stage slot t+2 (waited at END of step: ~2 steps lookahead) ----
    if (t + 2 < T_STEPS){
      const int sl2 = (t+2) & 3;
      const float* src = g_gi + ((size_t)(t+2)*N_ENV + e0)*G3;
      #pragma unroll
      for (int i = 0; i < 2; i++){
        int ci = g + 512*i;
        if (ci < 768){
          int e = ci / 96, c = ci % 96;
          cp16(giS + sl2*GISLOT + e*GISTR + 4*c, src + (size_t)e*G3 + 4*c);
        }
      }
      if (g < 2) cp16(mS + sl2*EPC + 4*g, masks + (size_t)(t+2)*N_ENV + e0 + 4*g);
    }
    asm volatile("cp.async.commit_group;");

    // ---- matvec partial: this k-half, 3 tiles x 3 products ----
    float acc[3][3][4];
    #pragma unroll
    for (int G = 0; G < 3; G++)
      #pragma unroll
      for (int p = 0; p < 3; p++)
        #pragma unroll
        for (int i = 0; i < 4; i++) acc[G][p][i] = 0.f;

    #pragma unroll
    for (int kd = 0; kd < 4; kd++){
      unsigned bh0 = lds32(hhib + kd*32);
      unsigned bh1 = lds32(hhib + kd*32 + 16);
      unsigned bl0 = lds32(hlob + kd*32);
      unsigned bl1 = lds32(hlob + kd*32 + 16);
      #pragma unroll
      for (int G = 0; G < 3; G++){
        unsigned wl[4];
        ldsm4(wl, lmb[G] + kd*32);
        hmma16(acc[G][0], whi[G][kd], bh0, bh1);
        hmma16(acc[G][1], whi[G][kd], bl0, bl1);
        hmma16(acc[G][2], wl,         bh0, bh1);
      }
    }
    float gh[3][4];
    #pragma unroll
    for (int G = 0; G < 3; G++)
      #pragma unroll
      for (int i = 0; i < 4; i++)
        gh[G][i] = (acc[G][0][i] + acc[G][1][i]) + acc[G][2][i];

    // ---- high half: publish partials ----
    if (!low){
      #pragma unroll
      for (int u = 0; u < 4; u++){
        const int j = (u < 2) ? J : J+8;
        const int e = (u & 1) ? E+1 : E;
        #pragma unroll
        for (int G = 0; G < 3; G++)
          ghpS[e*GISTR + G*128 + j] = gh[G][u];
      }
    }
    __syncthreads();   // partials + (h' from last step already synced)

    // ---- low half: combine + gates + h' ----
    if (low){
      const int sl = t & 3;
      const float* gib = giS + sl*GISLOT;
      const float m0 = mS[sl*EPC + E];
      const float m1 = mS[sl*EPC + E + 1];
      const bool last = (t == T_STEPS-1);

      #pragma unroll
      for (int u = 0; u < 4; u++){
        const int j = (u < 2) ? J : J+8;
        const int e = (u & 1) ? E+1 : E;
        const float m  = (u & 1) ? m1 : m0;
        const float bR = (u < 2) ? bR0 : bR1;
        const float bZ = (u < 2) ? bZ0 : bZ1;
        const float bN = (u < 2) ? bN0 : bN1;
        float hold = (u==0)?h00:(u==1)?h01:(u==2)?h10:h11;

        const float* php = ghpS + e*GISTR + j;
        float sR = gh[0][u] + php[0];
        float sZ = gh[1][u] + php[128];
        float sN = gh[2][u] + php[256];

        const float* gie = gib + e*GISTR;
        float cr = gie[j], cz = gie[128+j], cn = gie[256+j];
        float r = siga(cr + fmaf(m, sR, bR));
        float z = siga(cz + fmaf(m, sZ, bZ));
        float n = tanha(cn + r * fmaf(m, sN, bN));
        float hn = fmaf(z, fmaf(m, hold, -n), n);

        if (u==0) h00 = hn; else if (u==1) h01 = hn;
        else if (u==2) h10 = hn; else h11 = hn;

        __half hh = __float2half_rn(hn);
        hhiS[e*136 + j] = hh;
        hloS[e*136 + j] = __float2half_rn(hn - __half2float(hh));
        outs[(size_t)t*OUT_STRIDE + (size_t)(e0+e)*HID + j] = hn;
        if (last && h_final != nullptr)
          h_final[(size_t)(e0+e)*HID + j] = hn;
      }
    }

    asm volatile("cp.async.wait_group 1;");  // slot t+1 complete
    __syncthreads();                          // h' visible; ghp reusable
  }
}

// ---------------------------------------------------------------------------
extern "C" void kernel_launch(void* const* d_in, const int* in_sizes, int n_in,
                              void* d_out, int out_size){
  (void)in_sizes; (void)n_in;
  const float* x     = (const float*)d_in[0];
  const float* h0    = (const float*)d_in[1];
  const float* masks = (const float*)d_in[2];
  const float* w_ih  = (const float*)d_in[3];
  const float* w_hh  = (const float*)d_in[4];
  const float* b_ih  = (const float*)d_in[5];
  const float* b_hh  = (const float*)d_in[6];

  float* outs = (float*)d_out;
  float* hf = nullptr;
  if ((long long)out_size >= (long long)M_TOTAL*HID + (long long)N_ENV*HID)
    hf = outs + (size_t)M_TOTAL*HID;

  const int k1_smem = (3*128*LDA + 128) * (int)sizeof(float);
  cudaFuncSetAttribute(k1_gi, cudaFuncAttributeMaxDynamicSharedMemorySize, k1_smem);
  k1_gi<<<dim3(3,128), 256, k1_smem>>>(x, w_ih, b_ih);

  cudaFuncSetAttribute(k2_scan, cudaFuncAttributeMaxDynamicSharedMemorySize, K2_SMEM);
  k2_scan<<<NCTA2, 512, K2_SMEM>>>(h0, masks, w_hh, b_hh, outs, hf);
}

// round 14
// speedup vs baseline: 1.4272x; 1.4272x over previous
#include <cuda_runtime.h>
#include <cstdint>
#include <cstddef>

#define T_STEPS 2048
#define N_ENV   256
#define HID     128
#define G3      384          // 3*HID
#define IDIM    128
#define M_TOTAL (T_STEPS*N_ENV)   // 524288
#define LDA     132          // padded smem row (floats)
#define RING    4            // gi ring depth (steps)

// Scratch for gi = x @ w_ih^T + b_ih : [M_TOTAL, G3] fp32 (805 MB)
__device__ float g_gi[(size_t)M_TOTAL * G3];

// ---------------------------------------------------------------------------
// helpers
// ---------------------------------------------------------------------------
__device__ __forceinline__ unsigned f2tf(float f){
  unsigned u; asm("cvt.rna.tf32.f32 %0, %1;" : "=r"(u) : "f"(f)); return u;
}
__device__ __forceinline__ void mma8(float* c, const unsigned* a, const unsigned* b){
  asm volatile("mma.sync.aligned.m16n8k8.row.col.f32.tf32.tf32.f32 "
      "{%0,%1,%2,%3}, {%4,%5,%6,%7}, {%8,%9}, {%0,%1,%2,%3};"
      : "+f"(c[0]), "+f"(c[1]), "+f"(c[2]), "+f"(c[3])
      : "r"(a[0]), "r"(a[1]), "r"(a[2]), "r"(a[3]), "r"(b[0]), "r"(b[1]));
}
__device__ __forceinline__ void cp16(float* dst, const float* src){
  unsigned s = (unsigned)__cvta_generic_to_shared(dst);
  asm volatile("cp.async.cg.shared.global [%0], [%1], 16;" :: "r"(s), "l"(src));
}
__device__ __forceinline__ void cp8(float* dst, const float* src){
  unsigned s = (unsigned)__cvta_generic_to_shared(dst);
  asm volatile("cp.async.ca.shared.global [%0], [%1], 8;" :: "r"(s), "l"(src));
}
__device__ __forceinline__ unsigned long long pk2(float lo, float hi){
  unsigned long long r; asm("mov.b64 %0, {%1,%2};" : "=l"(r) : "f"(lo), "f"(hi)); return r;
}
__device__ __forceinline__ void fma2(unsigned long long& d, unsigned long long a, unsigned long long b){
  asm("fma.rn.f32x2 %0, %1, %2, %0;" : "+l"(d) : "l"(a), "l"(b));
}
__device__ __forceinline__ float2 upk(unsigned long long v){
  float lo, hi; asm("mov.b64 {%0,%1}, %2;" : "=f"(lo), "=f"(hi) : "l"(v));
  return make_float2(lo, hi);
}
// fast gates: MUFU.TANH (validated in R13: rel_err unchanged at 3.177e-4)
__device__ __forceinline__ float tanha(float x){
  float y; asm("tanh.approx.f32 %0, %1;" : "=f"(y) : "f"(x)); return y;
}
__device__ __forceinline__ float siga(float x){
  return fmaf(0.5f, tanha(0.5f*x), 0.5f);
}

// ---------------------------------------------------------------------------
// K1: gi = x @ w_ih^T + b_ih   (tf32 mma.sync) — exact R5 version
// ---------------------------------------------------------------------------
__global__ void __launch_bounds__(256) k1_gi(const float* __restrict__ x,
                                             const float* __restrict__ w_ih,
                                             const float* __restrict__ b_ih){
  extern __shared__ float sm[];
  float* Bs   = sm;
  float* As   = sm + 128*LDA;
  float* bias = sm + 3*128*LDA;

  const int tid  = threadIdx.x;
  const int nb   = blockIdx.x;
  const int slab = blockIdx.y;
  const int gbase = nb * 128;

  for (int idx = tid; idx < 128*32; idx += 256){
    int r = idx >> 5, c4 = idx & 31;
    float4 v = reinterpret_cast<const float4*>(w_ih + (size_t)(gbase + r)*IDIM)[c4];
    float* d = Bs + r*LDA + c4*4;
    d[0] = __uint_as_float(f2tf(v.x));
    d[1] = __uint_as_float(f2tf(v.y));
    d[2] = __uint_as_float(f2tf(v.z));
    d[3] = __uint_as_float(f2tf(v.w));
  }
  if (tid < 128) bias[tid] = b_ih[gbase + tid];

  const int lane = tid & 31, wid = tid >> 5;
  const int wm = wid >> 1, wn = wid & 1;
  const int grp = lane >> 2, qid = lane & 3;

  {
    const float* srcb = x + (size_t)slab * 128 * IDIM;
    #pragma unroll
    for (int i = 0; i < 16; i++){
      int c = tid + 256*i;
      int r = c >> 5, c16 = c & 31;
      cp16(As + r*LDA + c16*4, srcb + (size_t)r*IDIM + c16*4);
    }
    asm volatile("cp.async.commit_group;");
  }

  for (int it = 0; it < 32; it++){
    const int buf = it & 1;
    if (it + 1 < 32){
      int mt = slab + (it+1)*128;
      const float* srcb = x + (size_t)mt * 128 * IDIM;
      float* dstb = As + ((it+1)&1)*128*LDA;
      #pragma unroll
      for (int i = 0; i < 16; i++){
        int c = tid + 256*i;
        int r = c >> 5, c16 = c & 31;
        cp16(dstb + r*LDA + c16*4, srcb + (size_t)r*IDIM + c16*4);
      }
      asm volatile("cp.async.commit_group;");
      asm volatile("cp.async.wait_group 1;");
    } else {
      asm volatile("cp.async.wait_group 0;");
    }
    __syncthreads();

    float c[2][8][4];
    #pragma unroll
    for (int am=0;am<2;am++)
      #pragma unroll
      for(int an=0;an<8;an++)
        #pragma unroll
        for(int k=0;k<4;k++) c[am][an][k]=0.f;

    const float* A = As + buf*128*LDA;
    for (int k0 = 0; k0 < 128; k0 += 8){
      unsigned af[2][4];
      #pragma unroll
      for (int am=0; am<2; am++){
        int r0 = wm*32 + am*16 + grp;
        af[am][0] = f2tf(A[r0*LDA + k0 + qid]);
        af[am][1] = f2tf(A[(r0+8)*LDA + k0 + qid]);
        af[am][2] = f2tf(A[r0*LDA + k0 + qid + 4]);
        af[am][3] = f2tf(A[(r0+8)*LDA + k0 + qid + 4]);
      }
      unsigned bf[8][2];
      #pragma unroll
      for (int an=0; an<8; an++){
        int nr = wn*64 + an*8 + grp;
        bf[an][0] = __float_as_uint(Bs[nr*LDA + k0 + qid]);
        bf[an][1] = __float_as_uint(Bs[nr*LDA + k0 + qid + 4]);
      }
      #pragma unroll
      for (int am=0; am<2; am++)
        #pragma unroll
        for (int an=0; an<8; an++)
          mma8(c[am][an], af[am], bf[an]);
    }
    __syncthreads();

    const int mrow = (slab + it*128) * 128;
    #pragma unroll
    for (int am=0; am<2; am++){
      int r0 = mrow + wm*32 + am*16 + grp;
      #pragma unroll
      for (int an=0; an<8; an++){
        int colL = wn*64 + an*8 + 2*qid;
        float b0 = bias[colL], b1 = bias[colL+1];
        float2 v0 = make_float2(c[am][an][0]+b0, c[am][an][1]+b1);
        float2 v1 = make_float2(c[am][an][2]+b0, c[am][an][3]+b1);
        *reinterpret_cast<float2*>(&g_gi[(size_t)r0*G3 + gbase + colL]) = v0;
        *reinterpret_cast<float2*>(&g_gi[(size_t)(r0+8)*G3 + gbase + colL]) = v1;
      }
    }
  }
}

// ---------------------------------------------------------------------------
// K2: persistent GRU scan — EXACT R5 champion structure, with tanh.approx
// gates (only change). 128 CTAs x 384 threads, 2 envs per CTA.
// gi + masks staged via cp.async ring buffer, 2 steps of lookahead.
// Phase A(t): matvec env0 step t (all)  || gates env1 step t-1 (warps 0-3)
// Phase B(t): matvec env1 step t (all)  || gates env0 step t   (warps 0-3)
// ---------------------------------------------------------------------------
__device__ __forceinline__ void matvec_row(
    const unsigned long long* __restrict__ wq,
    const float* __restrict__ h_base, float* gh_dst)
{
  const ulonglong2* hp = reinterpret_cast<const ulonglong2*>(h_base);
  unsigned long long A0=0, A1=0, A2=0, A3=0;
  #pragma unroll
  for (int i = 0; i < 16; i++){
    ulonglong2 v0 = hp[2*i];
    fma2(A0, wq[4*i],   v0.x);
    fma2(A1, wq[4*i+1], v0.y);
    ulonglong2 v1 = hp[2*i+1];
    fma2(A2, wq[4*i+2], v1.x);
    fma2(A3, wq[4*i+3], v1.y);
  }
  float2 f0=upk(A0), f1=upk(A1), f2=upk(A2), f3=upk(A3);
  *gh_dst = ((f0.x+f0.y)+(f1.x+f1.y)) + ((f2.x+f2.y)+(f3.x+f3.y));
}

__global__ void __launch_bounds__(384, 1) k2_scan(
    const float* __restrict__ h0,
    const float* __restrict__ masks,
    const float* __restrict__ w_hh,
    const float* __restrict__ b_hh,
    float* __restrict__ outs,
    float* __restrict__ h_final)
{
  __shared__ __align__(16) float h_sm[2][HID];
  __shared__ float gh_sm[2][G3];
  __shared__ __align__(16) float gi_ring[RING][2][G3];   // [slot][env][row]
  __shared__ __align__(8)  float m_ring[RING][2];        // [slot][env]

  const int g  = threadIdx.x;
  const int j  = g & 127;
  const bool is_gate = (g < 128);
  const int e0 = blockIdx.x * 2;

  // w_hh row g, packed f32x2 (128 regs)
  unsigned long long wq[64];
  {
    const float4* wr = reinterpret_cast<const float4*>(w_hh + (size_t)g * HID);
    #pragma unroll
    for (int i = 0; i < 32; i++){
      float4 v = wr[i];
      wq[2*i]   = pk2(v.x, v.y);
      wq[2*i+1] = pk2(v.z, v.w);
    }
  }
  float bgr=0.f, bgz=0.f, bgn=0.f;
  if (is_gate){ bgr = b_hh[j]; bgz = b_hh[128+j]; bgn = b_hh[256+j]; }

  if (g < 256) h_sm[g>>7][j] = h0[(size_t)(e0 + (g>>7))*HID + j];

  const size_t STRIDE     = (size_t)N_ENV*G3;
  const size_t OUT_STRIDE = (size_t)N_ENV*HID;

  // cp.async staging assignment: threads 0..191 move one float4 of gi;
  // thread 192 moves both masks (8 bytes).
  const int  cpk   = g;
  const bool cp_gi = (cpk < 192);
  const int  cp_env = (cpk >= 96);
  const int  cp_off = (cpk - cp_env*96) * 4;
  const float* gi_src_base = g_gi + (size_t)(e0 + cp_env)*G3 + cp_off;
  const float* mk_src_base = masks + e0;

  // Prologue: stage steps 0 and 1 (two committed groups)
  #pragma unroll
  for (int pt = 0; pt < 2; pt++){
    if (cp_gi)      cp16(&gi_ring[pt][cp_env][cp_off], gi_src_base + (size_t)pt*STRIDE);
    else if (cpk == 192) cp8(&m_ring[pt][0], mk_src_base + (size_t)pt*N_ENV);
    asm volatile("cp.async.commit_group;");
  }
  __syncthreads();

  #pragma unroll 1
  for (int t = 0; t < T_STEPS; t++){
    // Stage step t+2 (slot (t+2)&3), then guarantee group t is complete.
    if (t + 2 < T_STEPS){
      const int sl = (t+2) & (RING-1);
      if (cp_gi)      cp16(&gi_ring[sl][cp_env][cp_off], gi_src_base + (size_t)(t+2)*STRIDE);
      else if (cpk == 192) cp8(&m_ring[sl][0], mk_src_base + (size_t)(t+2)*N_ENV);
    }
    asm volatile("cp.async.commit_group;");
    asm volatile("cp.async.wait_group 2;");   // group t done (visible after phase-A barrier)

    // ===== Phase A(t): gates env1 (step t-1) || matvec env0 (step t) =======
    if (is_gate && t > 0){
      const int sl = (t-1) & (RING-1);
      float cm = m_ring[sl][1];
      float cr = gi_ring[sl][1][j];
      float cz = gi_ring[sl][1][128+j];
      float cn = gi_ring[sl][1][256+j];
      float sr = gh_sm[1][j], sz = gh_sm[1][128+j], sn = gh_sm[1][256+j];
      float hold = h_sm[1][j];
      float r = siga(cr + fmaf(cm, sr, bgr));
      float z = siga(cz + fmaf(cm, sz, bgz));
      float n = tanha(cn + r * fmaf(cm, sn, bgn));
      float hn = fmaf(z, fmaf(cm, hold, -n), n);
      h_sm[1][j] = hn;
      outs[(size_t)(t-1)*OUT_STRIDE + (size_t)(e0+1)*HID + j] = hn;
    }
    matvec_row(wq, h_sm[0], &gh_sm[0][g]);
    __syncthreads();

    // ===== Phase B(t): gates env0 (step t) || matvec env1 (step t) =========
    if (is_gate){
      const int sl = t & (RING-1);
      float cm = m_ring[sl][0];
      float cr = gi_ring[sl][0][j];
      float cz = gi_ring[sl][0][128+j];
      float cn = gi_ring[sl][0][256+j];
      float sr = gh_sm[0][j], sz = gh_sm[0][128+j], sn = gh_sm[0][256+j];
      float hold = h_sm[0][j];
      float r = siga(cr + fmaf(cm, sr, bgr));
      float z = siga(cz + fmaf(cm, sz, bgz));
      float n = tanha(cn + r * fmaf(cm, sn, bgn));
      float hn = fmaf(z, fmaf(cm, hold, -n), n);
      h_sm[0][j] = hn;
      outs[(size_t)t*OUT_STRIDE + (size_t)e0*HID + j] = hn;
      if (t == T_STEPS-1 && h_final != nullptr)
        h_final[(size_t)e0*HID + j] = hn;
    }
    matvec_row(wq, h_sm[1], &gh_sm[1][g]);
    __syncthreads();
  }

  // ===== Epilogue: gates env1, step T-1 (slot (T-1)&3 completed) ===========
  if (is_gate){
    const int sl = (T_STEPS-1) & (RING-1);
    float cm = m_ring[sl][1];
    float cr = gi_ring[sl][1][j];
    float cz = gi_ring[sl][1][128+j];
    float cn = gi_ring[sl][1][256+j];
    float sr = gh_sm[1][j], sz = gh_sm[1][128+j], sn = gh_sm[1][256+j];
    float hold = h_sm[1][j];
    float r = siga(cr + fmaf(cm, sr, bgr));
    float z = siga(cz + fmaf(cm, sz, bgz));
    float n = tanha(cn + r * fmaf(cm, sn, bgn));
    float hn = fmaf(z, fmaf(cm, hold, -n), n);
    outs[(size_t)(T_STEPS-1)*OUT_STRIDE + (size_t)(e0+1)*HID + j] = hn;
    if (h_final != nullptr) h_final[(size_t)(e0+1)*HID + j] = hn;
  }
}

// ---------------------------------------------------------------------------
extern "C" void kernel_launch(void* const* d_in, const int* in_sizes, int n_in,
                              void* d_out, int out_size){
  (void)in_sizes; (void)n_in;
  const float* x     = (const float*)d_in[0];
  const float* h0    = (const float*)d_in[1];
  const float* masks = (const float*)d_in[2];
  const float* w_ih  = (const float*)d_in[3];
  const float* w_hh  = (const float*)d_in[4];
  const float* b_ih  = (const float*)d_in[5];
  const float* b_hh  = (const float*)d_in[6];

  float* outs = (float*)d_out;
  float* hf = nullptr;
  if ((long long)out_size >= (long long)M_TOTAL*HID + (long long)N_ENV*HID)
    hf = outs + (size_t)M_TOTAL*HID;

  const int k1_smem = (3*128*LDA + 128) * (int)sizeof(float);
  cudaFuncSetAttribute(k1_gi, cudaFuncAttributeMaxDynamicSharedMemorySize, k1_smem);
  k1_gi<<<dim3(3,128), 256, k1_smem>>>(x, w_ih, b_ih);
  k2_scan<<<128, 384>>>(h0, masks, w_hh, b_hh, outs, hf);
}